// round 14
// baseline (speedup 1.0000x reference)
#include <cuda_runtime.h>
#include <cuda_bf16.h>
#include <cstdint>
#include <math.h>

#define BATCH 4
#define CH 256
#define HW 4096
#define NHEAD 4
#define HDIM 64
#define NGROUP 32
#define CPG 8
#define QKV_M 768

// softmax scale folded into q at qkv epilogue: 1/sqrt(256) * log2(e)
#define QSCALE (0.0625f * 1.4426950408889634f)
#define INV_SQRT2 0.70710678118654752f

// scratch (device globals: no allocations allowed)
__device__ __nv_bfloat16 g_norm[BATCH * CH * HW];
__device__ __nv_bfloat16 g_qkv [BATCH * QKV_M * HW];
__device__ __nv_bfloat16 g_att [BATCH * CH * HW];
__device__ __nv_bfloat16 g_wq  [QKV_M * CH];
__device__ __nv_bfloat16 g_wo  [CH * CH];

// ======================= PTX helpers (sm_100 baseline ISA) =================
__device__ __forceinline__ uint32_t smem_u32(const void* p) {
    uint32_t a;
    asm("{ .reg .u64 t; cvta.to.shared.u64 t, %1; cvt.u32.u64 %0, t; }" : "=r"(a) : "l"(p));
    return a;
}
__device__ __forceinline__ uint32_t swz(uint32_t off) {     // 16B-unit XOR swizzle, 128B rows
    return off ^ ((off >> 3) & 0x70u);
}
#define CP16(dst, src) \
    asm volatile("cp.async.ca.shared.global [%0], [%1], 16;" :: "r"(dst), "l"(src) : "memory")
#define CP_COMMIT() asm volatile("cp.async.commit_group;" ::: "memory")
#define CP_WAIT1()  asm volatile("cp.async.wait_group 1;" ::: "memory")
#define CP_WAIT0()  asm volatile("cp.async.wait_group 0;" ::: "memory")

__device__ __forceinline__ void ldsm_x4(uint32_t* f, uint32_t addr) {
    asm volatile("ldmatrix.sync.aligned.m8n8.x4.shared.b16 {%0,%1,%2,%3}, [%4];"
        : "=r"(f[0]), "=r"(f[1]), "=r"(f[2]), "=r"(f[3]) : "r"(addr));
}
__device__ __forceinline__ void ldsm_x4_t(uint32_t* f, uint32_t addr) {
    asm volatile("ldmatrix.sync.aligned.m8n8.x4.trans.shared.b16 {%0,%1,%2,%3}, [%4];"
        : "=r"(f[0]), "=r"(f[1]), "=r"(f[2]), "=r"(f[3]) : "r"(addr));
}
__device__ __forceinline__ void mma16816(float* d, const uint32_t* a, uint32_t b0, uint32_t b1) {
    asm volatile("mma.sync.aligned.m16n8k16.row.col.f32.bf16.bf16.f32 "
        "{%0,%1,%2,%3}, {%4,%5,%6,%7}, {%8,%9}, {%0,%1,%2,%3};"
        : "+f"(d[0]), "+f"(d[1]), "+f"(d[2]), "+f"(d[3])
        : "r"(a[0]), "r"(a[1]), "r"(a[2]), "r"(a[3]), "r"(b0), "r"(b1));
}
__device__ __forceinline__ float ex2(float x) {     // MUFU path
    float r; asm("ex2.approx.ftz.f32 %0, %1;" : "=f"(r) : "f"(x)); return r;
}
// FMA-pipe exp2: magic-number integer split + cubic poly on [-0.5, 0.5].
// rel err ~6e-4, far below bf16 P quantization. Runs on the idle FMA/ALU pipes.
__device__ __forceinline__ float ex2f(float x) {
    float t = __fadd_rn(x, 12582912.f);              // 1.5*2^23: RN to integer
    int   e = __float_as_int(t) - 0x4B400000;        // integer part of x
    float f = __fsub_rn(x, __fsub_rn(t, 12582912.f)); // frac in [-0.5, 0.5]
    float p = fmaf(f, 0.0555041087f, 0.2402264476f);
    p = fmaf(f, p, 0.6931471806f);
    p = fmaf(f, p, 1.0000000000f);
    return __int_as_float(__float_as_int(p) + (e << 23));
}
__device__ __forceinline__ uint32_t packbf(float lo, float hi) {
    uint32_t r; asm("cvt.rn.bf16x2.f32 %0, %1, %2;" : "=r"(r) : "f"(hi), "f"(lo)); return r;
}

// ---------------------------------------------------------------------------
// GroupNorm -> bf16 (blocks 0..127) fused with weight conversion (blocks 128+)
// ---------------------------------------------------------------------------
__global__ void gn_wconv_kernel(const float* __restrict__ x,
                                const float* __restrict__ gamma,
                                const float* __restrict__ beta,
                                __nv_bfloat16* __restrict__ out,
                                const float* __restrict__ wq, const float* __restrict__ wo,
                                __nv_bfloat16* __restrict__ wqb, __nv_bfloat16* __restrict__ wob) {
    if (blockIdx.x >= BATCH * NGROUP) {
        int i = (blockIdx.x - BATCH * NGROUP) * 256 + threadIdx.x;
        if (i < QKV_M * CH) wqb[i] = __float2bfloat16(wq[i]);
        if (i < CH * CH)    wob[i] = __float2bfloat16(wo[i]);
        return;
    }
    int b = blockIdx.x >> 5;
    int g = blockIdx.x & 31;
    const float* base = x + ((size_t)b * CH + g * CPG) * HW;
    __nv_bfloat16* obase = out + ((size_t)b * CH + g * CPG) * HW;
    int tid = threadIdx.x;

    float s = 0.f, ss = 0.f;
    for (int i = tid; i < CPG * HW; i += 256) {
        float v = base[i];
        s += v; ss += v * v;
    }
    __shared__ float rs[8], rss[8];
    #pragma unroll
    for (int m = 16; m; m >>= 1) {
        s  += __shfl_xor_sync(0xffffffffu, s,  m);
        ss += __shfl_xor_sync(0xffffffffu, ss, m);
    }
    if ((tid & 31) == 0) { rs[tid >> 5] = s; rss[tid >> 5] = ss; }
    __syncthreads();
    if (tid < 32) {
        s  = (tid < 8) ? rs[tid]  : 0.f;
        ss = (tid < 8) ? rss[tid] : 0.f;
        #pragma unroll
        for (int m = 4; m; m >>= 1) {
            s  += __shfl_xor_sync(0xffffffffu, s,  m);
            ss += __shfl_xor_sync(0xffffffffu, ss, m);
        }
        if (tid == 0) { rs[0] = s; rss[0] = ss; }
    }
    __syncthreads();
    const float invN = 1.f / (float)(CPG * HW);
    float mean = rs[0] * invN;
    float var  = rss[0] * invN - mean * mean;
    float rinv = rsqrtf(var + 1e-5f);

    for (int i = tid * 2; i < CPG * HW; i += 512) {
        int c = g * CPG + (i >> 12);
        float a = (base[i]     - mean) * rinv * gamma[c] + beta[c];
        float d = (base[i + 1] - mean) * rinv * gamma[c] + beta[c];
        *(__nv_bfloat162*)&obase[i] = __floats2bfloat162_rn(a, d);
    }
}

// ---------------------------------------------------------------------------
// bf16 tensor-core GEMM (R12-proven): 256(M) x 64(T) tile, 256 threads.
// ---------------------------------------------------------------------------
#define SW0 0u
#define SX0 32768u
#define SW1 40960u
#define SX1 73728u
#define GEMM_SMEM 81920

__global__ void __launch_bounds__(256)
gemm_bf16(const __nv_bfloat16* __restrict__ W, const __nv_bfloat16* __restrict__ X,
          const float* __restrict__ bias, void* __restrict__ Y,
          int M, int mode, const float* __restrict__ resid) {
    extern __shared__ __align__(128) char sm[];
    uint32_t sb = smem_u32(sm);
    int tid = threadIdx.x, warp = tid >> 5, lane = tid & 31;
    int t0 = blockIdx.x * 64, m0 = blockIdx.y * 256, b = blockIdx.z;
    const __nv_bfloat16* Xb = X + (size_t)b * CH * HW;

    #pragma unroll
    for (int i = 0; i < 8; i++) {
        int u = tid + i * 256;
        int row = u >> 3, cb = u & 7;
        uint32_t so = swz((uint32_t)(row * 128 + cb * 16));
        CP16(sb + SW0 + so, W + (size_t)(m0 + row) * CH + cb * 8);
    }
    #pragma unroll
    for (int i = 0; i < 2; i++) {
        int u = tid + i * 256;
        int row = u >> 3, cb = u & 7;
        uint32_t so = swz((uint32_t)(row * 128 + cb * 16));
        CP16(sb + SX0 + so, Xb + (size_t)row * HW + t0 + cb * 8);
    }
    CP_COMMIT();

    int g = lane >> 3, r = lane & 7;
    uint32_t aoff0 = (uint32_t)((warp * 32 + (g & 1) * 8 + r) * 128 + (g >> 1) * 16);
    uint32_t aoff1 = aoff0 + 16 * 128;
    uint32_t boff  = (uint32_t)(((g & 1) * 8 + r) * 128 + (g >> 1) * 16);

    float acc0[8][4] = {}, acc1[8][4] = {};

    #pragma unroll
    for (int ck = 0; ck < 4; ck++) {
        if (ck < 3) {
            int c0 = (ck + 1) * 64;
            uint32_t wb = ((ck + 1) & 1) ? SW1 : SW0;
            uint32_t xs = ((ck + 1) & 1) ? SX1 : SX0;
            #pragma unroll
            for (int i = 0; i < 8; i++) {
                int u = tid + i * 256;
                int row = u >> 3, cb = u & 7;
                uint32_t so = swz((uint32_t)(row * 128 + cb * 16));
                CP16(sb + wb + so, W + (size_t)(m0 + row) * CH + c0 + cb * 8);
            }
            #pragma unroll
            for (int i = 0; i < 2; i++) {
                int u = tid + i * 256;
                int row = u >> 3, cb = u & 7;
                uint32_t so = swz((uint32_t)(row * 128 + cb * 16));
                CP16(sb + xs + so, Xb + (size_t)(c0 + row) * HW + t0 + cb * 8);
            }
            CP_COMMIT();
            CP_WAIT1();
        } else {
            CP_WAIT0();
        }
        __syncthreads();
        uint32_t Wb = sb + ((ck & 1) ? SW1 : SW0);
        uint32_t Xs = sb + ((ck & 1) ? SX1 : SX0);
        #pragma unroll
        for (int ks = 0; ks < 4; ks++) {
            uint32_t af0[4], af1[4];
            ldsm_x4(af0, Wb + swz(aoff0 + ks * 32));
            ldsm_x4(af1, Wb + swz(aoff1 + ks * 32));
            #pragma unroll
            for (int jj = 0; jj < 4; jj++) {
                uint32_t bf[4];
                ldsm_x4_t(bf, Xs + swz(boff + ks * 2048 + jj * 32));
                mma16816(acc0[2 * jj],     af0, bf[0], bf[1]);
                mma16816(acc0[2 * jj + 1], af0, bf[2], bf[3]);
                mma16816(acc1[2 * jj],     af1, bf[0], bf[1]);
                mma16816(acc1[2 * jj + 1], af1, bf[2], bf[3]);
            }
        }
        __syncthreads();
    }

    int r0 = warp * 32 + (lane >> 2);
    int cc = (lane & 3) * 2;
    int mA0 = m0 + r0, mB0 = mA0 + 8, mA1 = mA0 + 16, mB1 = mA0 + 24;
    float bA0 = bias[mA0], bB0 = bias[mB0], bA1 = bias[mA1], bB1 = bias[mB1];

    if (mode == 0) {
        float sA0 = ((mA0 % 192) < HDIM) ? QSCALE : 1.f;
        float sB0 = ((mB0 % 192) < HDIM) ? QSCALE : 1.f;
        float sA1 = ((mA1 % 192) < HDIM) ? QSCALE : 1.f;
        float sB1 = ((mB1 % 192) < HDIM) ? QSCALE : 1.f;
        #pragma unroll
        for (int nb = 0; nb < 8; nb++) {
            int col = nb * 8 + cc;
            *(uint32_t*)(sm + r0 * 144 + col * 2) =
                packbf((acc0[nb][0] + bA0) * sA0, (acc0[nb][1] + bA0) * sA0);
            *(uint32_t*)(sm + (r0 + 8) * 144 + col * 2) =
                packbf((acc0[nb][2] + bB0) * sB0, (acc0[nb][3] + bB0) * sB0);
            *(uint32_t*)(sm + (r0 + 16) * 144 + col * 2) =
                packbf((acc1[nb][0] + bA1) * sA1, (acc1[nb][1] + bA1) * sA1);
            *(uint32_t*)(sm + (r0 + 24) * 144 + col * 2) =
                packbf((acc1[nb][2] + bB1) * sB1, (acc1[nb][3] + bB1) * sB1);
        }
        __syncthreads();
        __nv_bfloat16* Yb = (__nv_bfloat16*)Y + ((size_t)b * M + m0) * HW + t0;
        #pragma unroll
        for (int i = 0; i < 8; i++) {
            int u = tid + i * 256;
            int row = u >> 3, cb = u & 7;
            uint4 v = *(const uint4*)(sm + row * 144 + cb * 16);
            *(uint4*)(Yb + (size_t)row * HW + cb * 8) = v;
        }
    } else {
        float* Of = (float*)sm;
        #pragma unroll
        for (int nb = 0; nb < 8; nb++) {
            int col = nb * 8 + cc;
            Of[r0 * 68 + col]            = acc0[nb][0] + bA0;
            Of[r0 * 68 + col + 1]        = acc0[nb][1] + bA0;
            Of[(r0 + 8) * 68 + col]      = acc0[nb][2] + bB0;
            Of[(r0 + 8) * 68 + col + 1]  = acc0[nb][3] + bB0;
            Of[(r0 + 16) * 68 + col]     = acc1[nb][0] + bA1;
            Of[(r0 + 16) * 68 + col + 1] = acc1[nb][1] + bA1;
            Of[(r0 + 24) * 68 + col]     = acc1[nb][2] + bB1;
            Of[(r0 + 24) * 68 + col + 1] = acc1[nb][3] + bB1;
        }
        __syncthreads();
        float* Yo = (float*)Y + ((size_t)b * M + m0) * HW + t0;
        const float* Xr = resid + ((size_t)b * CH + m0) * HW + t0;
        #pragma unroll
        for (int i = 0; i < 16; i++) {
            int u = tid + i * 256;
            int row = u >> 4, q4 = u & 15;
            float4 v  = *(const float4*)&Of[row * 68 + q4 * 4];
            float4 xr = *(const float4*)(Xr + (size_t)row * HW + q4 * 4);
            v.x = (v.x + xr.x) * INV_SQRT2;
            v.y = (v.y + xr.y) * INV_SQRT2;
            v.z = (v.z + xr.z) * INV_SQRT2;
            v.w = (v.w + xr.w) * INV_SQRT2;
            *(float4*)(Yo + (size_t)row * HW + q4 * 4) = v;
        }
    }
}

// ---------------------------------------------------------------------------
// mma.sync flash attention (R8/R12-proven structure): 32 q-rows/warp, 3-stage
// KV ring, one barrier per chunk, all-S-upfront then softmax(16)->PV(16) x4.
// NEW: exp2 split across pipes — kk even uses MUFU ex2.approx, kk odd uses
// FMA-pipe polynomial exp2, balancing the co-saturated MUFU against the
// near-idle FMA pipe so the tensor pipe becomes the sole bottleneck.
// ---------------------------------------------------------------------------
#define SQ0 0u
#define SQ1 8192u
#define KVS(s) (16384u + (uint32_t)(s) * 16384u)   // stage s: K at +0, V at +8192
#define ATT_SMEM 65536

__global__ void __launch_bounds__(128, 2)
attn_kernel(const __nv_bfloat16* __restrict__ qkv, __nv_bfloat16* __restrict__ out) {
    extern __shared__ __align__(128) char sm[];
    uint32_t sb = smem_u32(sm);
    int tid = threadIdx.x, warp = tid >> 5, lane = tid & 31;
    int qt0 = blockIdx.x * 128, h = blockIdx.y, b = blockIdx.z;

    const __nv_bfloat16* qb = qkv + ((size_t)(b * QKV_M + h * 192)) * HW;
    const __nv_bfloat16* kb = qb + (size_t)HDIM * HW;
    const __nv_bfloat16* vb = kb + (size_t)HDIM * HW;

    #pragma unroll
    for (int i = 0; i < 4; i++) {
        int u = tid + i * 128;
        int d = u >> 3, ub = u & 7;
        uint32_t so = swz((uint32_t)(d * 128 + ub * 16));
        CP16(sb + SQ0 + so,           qb + (size_t)d * HW + qt0 + ub * 8);
        CP16(sb + SQ1 + so,           qb + (size_t)d * HW + qt0 + 64 + ub * 8);
        CP16(sb + KVS(0) + so,        kb + (size_t)d * HW + ub * 8);
        CP16(sb + KVS(0) + 8192 + so, vb + (size_t)d * HW + ub * 8);
    }
    CP_COMMIT();
    #pragma unroll
    for (int i = 0; i < 4; i++) {
        int u = tid + i * 128;
        int d = u >> 3, ub = u & 7;
        uint32_t so = swz((uint32_t)(d * 128 + ub * 16));
        CP16(sb + KVS(1) + so,        kb + (size_t)d * HW + 64 + ub * 8);
        CP16(sb + KVS(1) + 8192 + so, vb + (size_t)d * HW + 64 + ub * 8);
    }
    CP_COMMIT();

    int g = lane >> 3, r = lane & 7;
    uint32_t koff = (uint32_t)(((g & 1) * 8 + r) * 128 + (g >> 1) * 16);
    uint32_t voff = (uint32_t)(((g >> 1) * 8 + r) * 128 + (g & 1) * 16);
    uint32_t qtile = (warp < 2) ? SQ0 : SQ1;
    int qcol = (warp & 1) * 32;
    uint32_t qoff0 = (uint32_t)(((g >> 1) * 8 + r) * 128 + (qcol + (g & 1) * 8) * 2);
    uint32_t qoff1 = qoff0 + 32;   // +16 queries * 2B

    float o0[8][4] = {}, o1[8][4] = {};
    float l[4] = {};
    uint32_t qa[2][4][4];

    for (int kt = 0; kt < 64; kt++) {
        if (kt < 63) { CP_WAIT1(); } else { CP_WAIT0(); }
        __syncthreads();
        if (kt + 2 < 64) {
            uint32_t st = KVS((kt + 2) % 3);
            const __nv_bfloat16* kc = kb + (kt + 2) * 64;
            const __nv_bfloat16* vc = vb + (kt + 2) * 64;
            #pragma unroll
            for (int i = 0; i < 4; i++) {
                int u = tid + i * 128;
                int d = u >> 3, ub = u & 7;
                uint32_t so = swz((uint32_t)(d * 128 + ub * 16));
                CP16(sb + st + so,        kc + (size_t)d * HW + ub * 8);
                CP16(sb + st + 8192 + so, vc + (size_t)d * HW + ub * 8);
            }
            CP_COMMIT();
        }

        uint32_t Kb = sb + KVS(kt % 3);
        uint32_t Vb = Kb + 8192;

        if (kt == 0) {
            #pragma unroll
            for (int ks = 0; ks < 4; ks++) {
                ldsm_x4_t(qa[0][ks], sb + qtile + swz(qoff0 + ks * 2048));
                ldsm_x4_t(qa[1][ks], sb + qtile + swz(qoff1 + ks * 2048));
            }
        }

        // ---- S = Q K^T for all 64 keys (both query sets)
        float s0[8][4] = {}, s1[8][4] = {};
        #pragma unroll
        for (int ks = 0; ks < 4; ks++) {
            #pragma unroll
            for (int jj = 0; jj < 4; jj++) {
                uint32_t f[4];
                ldsm_x4_t(f, Kb + swz(koff + ks * 2048 + jj * 32));
                mma16816(s0[2 * jj],     qa[0][ks], f[0], f[1]);
                mma16816(s0[2 * jj + 1], qa[0][ks], f[2], f[3]);
                mma16816(s1[2 * jj],     qa[1][ks], f[0], f[1]);
                mma16816(s1[2 * jj + 1], qa[1][ks], f[2], f[3]);
            }
        }

        // ---- interleaved: softmax(16 keys) then PV(16 keys), x4.
        //      exp2 pipe split: kk even -> MUFU, kk odd -> FMA poly.
        #pragma unroll
        for (int kk = 0; kk < 4; kk++) {
            uint32_t pk0[2][2], pk1[2][2];
            #pragma unroll
            for (int jj = 0; jj < 2; jj++) {
                int j = 2 * kk + jj;
                float a0, a1, a2, a3, b0, b1, b2, b3;
                if ((kk & 1) == 0) {
                    a0 = ex2(s0[j][0]); a1 = ex2(s0[j][1]);
                    a2 = ex2(s0[j][2]); a3 = ex2(s0[j][3]);
                    b0 = ex2(s1[j][0]); b1 = ex2(s1[j][1]);
                    b2 = ex2(s1[j][2]); b3 = ex2(s1[j][3]);
                } else {
                    a0 = ex2f(s0[j][0]); a1 = ex2f(s0[j][1]);
                    a2 = ex2f(s0[j][2]); a3 = ex2f(s0[j][3]);
                    b0 = ex2f(s1[j][0]); b1 = ex2f(s1[j][1]);
                    b2 = ex2f(s1[j][2]); b3 = ex2f(s1[j][3]);
                }
                l[0] += a0 + a1; l[1] += a2 + a3;
                pk0[jj][0] = packbf(a0, a1); pk0[jj][1] = packbf(a2, a3);
                l[2] += b0 + b1; l[3] += b2 + b3;
                pk1[jj][0] = packbf(b0, b1); pk1[jj][1] = packbf(b2, b3);
            }
            uint32_t A0[4] = { pk0[0][0], pk0[0][1], pk0[1][0], pk0[1][1] };
            uint32_t A1[4] = { pk1[0][0], pk1[0][1], pk1[1][0], pk1[1][1] };
            #pragma unroll
            for (int dd = 0; dd < 4; dd++) {
                uint32_t f[4];
                ldsm_x4(f, Vb + swz(voff + dd * 2048 + kk * 32));
                mma16816(o0[2 * dd],     A0, f[0], f[1]);
                mma16816(o0[2 * dd + 1], A0, f[2], f[3]);
                mma16816(o1[2 * dd],     A1, f[0], f[1]);
                mma16816(o1[2 * dd + 1], A1, f[2], f[3]);
            }
        }
    }

    // ---- epilogue
    #pragma unroll
    for (int i = 0; i < 4; i++) {
        l[i] += __shfl_xor_sync(0xffffffffu, l[i], 1);
        l[i] += __shfl_xor_sync(0xffffffffu, l[i], 2);
    }
    float i0 = 1.f / l[0], i1 = 1.f / l[1], i2 = 1.f / l[2], i3 = 1.f / l[3];

    __syncthreads();
    float* Os = (float*)sm;                 // [64 d][132] fp32 (33.8KB reuse)
    int r0 = warp * 32 + (lane >> 2);
    int cc = (lane & 3) * 2;
    #pragma unroll
    for (int nb = 0; nb < 8; nb++) {
        int d0 = nb * 8 + cc;
        Os[d0 * 132 + r0]            = o0[nb][0] * i0;
        Os[(d0 + 1) * 132 + r0]      = o0[nb][1] * i0;
        Os[d0 * 132 + r0 + 8]        = o0[nb][2] * i1;
        Os[(d0 + 1) * 132 + r0 + 8]  = o0[nb][3] * i1;
        Os[d0 * 132 + r0 + 16]       = o1[nb][0] * i2;
        Os[(d0 + 1) * 132 + r0 + 16] = o1[nb][1] * i2;
        Os[d0 * 132 + r0 + 24]       = o1[nb][2] * i3;
        Os[(d0 + 1) * 132 + r0 + 24] = o1[nb][3] * i3;
    }
    __syncthreads();
    __nv_bfloat16* ob = out + ((size_t)(b * CH + h * HDIM)) * HW + qt0;
    #pragma unroll
    for (int i = 0; i < 16; i++) {
        int e = tid + i * 128;
        int d = e >> 5, q4 = e & 31;
        float4 v = *(const float4*)&Os[d * 132 + q4 * 4];
        uint2 w;
        w.x = packbf(v.x, v.y);
        w.y = packbf(v.z, v.w);
        *(uint2*)(ob + (size_t)d * HW + q4 * 4) = w;
    }
}

// ---------------------------------------------------------------------------
extern "C" void kernel_launch(void* const* d_in, const int* in_sizes, int n_in,
                              void* d_out, int out_size) {
    const float* x     = (const float*)d_in[0];
    const float* gamma = (const float*)d_in[1];
    const float* beta  = (const float*)d_in[2];
    const float* w_qkv = (const float*)d_in[3];
    const float* b_qkv = (const float*)d_in[4];
    const float* w_out = (const float*)d_in[5];
    const float* b_out = (const float*)d_in[6];
    float* out = (float*)d_out;

    __nv_bfloat16 *norm, *qkv, *att, *wq, *wo;
    cudaGetSymbolAddress((void**)&norm, g_norm);
    cudaGetSymbolAddress((void**)&qkv,  g_qkv);
    cudaGetSymbolAddress((void**)&att,  g_att);
    cudaGetSymbolAddress((void**)&wq,   g_wq);
    cudaGetSymbolAddress((void**)&wo,   g_wo);

    cudaFuncSetAttribute(attn_kernel, cudaFuncAttributeMaxDynamicSharedMemorySize, ATT_SMEM);
    cudaFuncSetAttribute(gemm_bf16, cudaFuncAttributeMaxDynamicSharedMemorySize, GEMM_SMEM);

    gn_wconv_kernel<<<BATCH * NGROUP + QKV_M * CH / 256, 256>>>(
        x, gamma, beta, norm, w_qkv, w_out, wq, wo);
    gemm_bf16<<<dim3(HW / 64, QKV_M / 256, BATCH), 256, GEMM_SMEM>>>(wq, norm, b_qkv, qkv, QKV_M, 0, nullptr);
    attn_kernel<<<dim3(HW / 128, NHEAD, BATCH), 128, ATT_SMEM>>>(qkv, att);
    gemm_bf16<<<dim3(HW / 64, CH / 256, BATCH), 256, GEMM_SMEM>>>(wo, att, b_out, out, CH, 1, x);
}

// round 15
// speedup vs baseline: 1.1063x; 1.1063x over previous
#include <cuda_runtime.h>
#include <cuda_bf16.h>
#include <cstdint>
#include <math.h>

#define BATCH 4
#define CH 256
#define HW 4096
#define NHEAD 4
#define HDIM 64
#define NGROUP 32
#define CPG 8
#define QKV_M 768

// softmax scale folded into q at qkv epilogue: 1/sqrt(256) * log2(e)
#define QSCALE (0.0625f * 1.4426950408889634f)
#define INV_SQRT2 0.70710678118654752f

// scratch (device globals: no allocations allowed)
__device__ __nv_bfloat16 g_norm[BATCH * CH * HW];
__device__ __nv_bfloat16 g_qkv [BATCH * QKV_M * HW];
__device__ __nv_bfloat16 g_att [BATCH * CH * HW];
__device__ __nv_bfloat16 g_wq  [QKV_M * CH];
__device__ __nv_bfloat16 g_wo  [CH * CH];

// ======================= PTX helpers (sm_100 baseline ISA) =================
__device__ __forceinline__ uint32_t smem_u32(const void* p) {
    uint32_t a;
    asm("{ .reg .u64 t; cvta.to.shared.u64 t, %1; cvt.u32.u64 %0, t; }" : "=r"(a) : "l"(p));
    return a;
}
__device__ __forceinline__ uint32_t swz(uint32_t off) {     // 16B-unit XOR swizzle, 128B rows
    return off ^ ((off >> 3) & 0x70u);
}
#define CP16(dst, src) \
    asm volatile("cp.async.ca.shared.global [%0], [%1], 16;" :: "r"(dst), "l"(src) : "memory")
#define CP_COMMIT() asm volatile("cp.async.commit_group;" ::: "memory")
#define CP_WAIT1()  asm volatile("cp.async.wait_group 1;" ::: "memory")
#define CP_WAIT0()  asm volatile("cp.async.wait_group 0;" ::: "memory")

__device__ __forceinline__ void ldsm_x4(uint32_t* f, uint32_t addr) {
    asm volatile("ldmatrix.sync.aligned.m8n8.x4.shared.b16 {%0,%1,%2,%3}, [%4];"
        : "=r"(f[0]), "=r"(f[1]), "=r"(f[2]), "=r"(f[3]) : "r"(addr));
}
__device__ __forceinline__ void ldsm_x4_t(uint32_t* f, uint32_t addr) {
    asm volatile("ldmatrix.sync.aligned.m8n8.x4.trans.shared.b16 {%0,%1,%2,%3}, [%4];"
        : "=r"(f[0]), "=r"(f[1]), "=r"(f[2]), "=r"(f[3]) : "r"(addr));
}
__device__ __forceinline__ void mma16816(float* d, const uint32_t* a, uint32_t b0, uint32_t b1) {
    asm volatile("mma.sync.aligned.m16n8k16.row.col.f32.bf16.bf16.f32 "
        "{%0,%1,%2,%3}, {%4,%5,%6,%7}, {%8,%9}, {%0,%1,%2,%3};"
        : "+f"(d[0]), "+f"(d[1]), "+f"(d[2]), "+f"(d[3])
        : "r"(a[0]), "r"(a[1]), "r"(a[2]), "r"(a[3]), "r"(b0), "r"(b1));
}
__device__ __forceinline__ float ex2(float x) {
    float r; asm("ex2.approx.ftz.f32 %0, %1;" : "=f"(r) : "f"(x)); return r;
}
__device__ __forceinline__ uint32_t packbf(float lo, float hi) {
    uint32_t r; asm("cvt.rn.bf16x2.f32 %0, %1, %2;" : "=r"(r) : "f"(hi), "f"(lo)); return r;
}

// ---------------------------------------------------------------------------
// GroupNorm -> bf16 (blocks 0..127, float4-vectorized) fused with weight
// conversion (blocks 128+).
// ---------------------------------------------------------------------------
__global__ void gn_wconv_kernel(const float* __restrict__ x,
                                const float* __restrict__ gamma,
                                const float* __restrict__ beta,
                                __nv_bfloat16* __restrict__ out,
                                const float* __restrict__ wq, const float* __restrict__ wo,
                                __nv_bfloat16* __restrict__ wqb, __nv_bfloat16* __restrict__ wob) {
    if (blockIdx.x >= BATCH * NGROUP) {
        int i = (blockIdx.x - BATCH * NGROUP) * 256 + threadIdx.x;
        if (i < QKV_M * CH) wqb[i] = __float2bfloat16(wq[i]);
        if (i < CH * CH)    wob[i] = __float2bfloat16(wo[i]);
        return;
    }
    int b = blockIdx.x >> 5;
    int g = blockIdx.x & 31;
    const float4* base4 = (const float4*)(x + ((size_t)b * CH + g * CPG) * HW);
    __nv_bfloat16* obase = out + ((size_t)b * CH + g * CPG) * HW;
    int tid = threadIdx.x;

    // pass 1: sums over 8192 float4s (32 per thread)
    float s = 0.f, ss = 0.f;
    #pragma unroll 8
    for (int i = tid; i < CPG * HW / 4; i += 256) {
        float4 v = base4[i];
        s  += (v.x + v.y) + (v.z + v.w);
        ss += (v.x * v.x + v.y * v.y) + (v.z * v.z + v.w * v.w);
    }
    __shared__ float rs[8], rss[8];
    #pragma unroll
    for (int m = 16; m; m >>= 1) {
        s  += __shfl_xor_sync(0xffffffffu, s,  m);
        ss += __shfl_xor_sync(0xffffffffu, ss, m);
    }
    if ((tid & 31) == 0) { rs[tid >> 5] = s; rss[tid >> 5] = ss; }
    __syncthreads();
    if (tid < 32) {
        s  = (tid < 8) ? rs[tid]  : 0.f;
        ss = (tid < 8) ? rss[tid] : 0.f;
        #pragma unroll
        for (int m = 4; m; m >>= 1) {
            s  += __shfl_xor_sync(0xffffffffu, s,  m);
            ss += __shfl_xor_sync(0xffffffffu, ss, m);
        }
        if (tid == 0) { rs[0] = s; rss[0] = ss; }
    }
    __syncthreads();
    const float invN = 1.f / (float)(CPG * HW);
    float mean = rs[0] * invN;
    float var  = rss[0] * invN - mean * mean;
    float rinv = rsqrtf(var + 1e-5f);

    // pass 2: normalize, 1 float4 -> 4 bf16 (uint2) per iteration
    #pragma unroll 8
    for (int i4 = tid; i4 < CPG * HW / 4; i4 += 256) {
        int c = g * CPG + (i4 >> 10);           // (i4*4)>>12
        float sc = rinv * gamma[c];
        float sh = beta[c] - mean * sc;
        float4 v = base4[i4];
        uint2 w;
        w.x = packbf(fmaf(v.x, sc, sh), fmaf(v.y, sc, sh));
        w.y = packbf(fmaf(v.z, sc, sh), fmaf(v.w, sc, sh));
        *(uint2*)&obase[i4 * 4] = w;
    }
}

// ---------------------------------------------------------------------------
// bf16 tensor-core GEMM (R12-proven): 256(M) x 64(T) tile, 256 threads.
// ---------------------------------------------------------------------------
#define SW0 0u
#define SX0 32768u
#define SW1 40960u
#define SX1 73728u
#define GEMM_SMEM 81920

__global__ void __launch_bounds__(256)
gemm_bf16(const __nv_bfloat16* __restrict__ W, const __nv_bfloat16* __restrict__ X,
          const float* __restrict__ bias, void* __restrict__ Y,
          int M, int mode, const float* __restrict__ resid) {
    extern __shared__ __align__(128) char sm[];
    uint32_t sb = smem_u32(sm);
    int tid = threadIdx.x, warp = tid >> 5, lane = tid & 31;
    int t0 = blockIdx.x * 64, m0 = blockIdx.y * 256, b = blockIdx.z;
    const __nv_bfloat16* Xb = X + (size_t)b * CH * HW;

    #pragma unroll
    for (int i = 0; i < 8; i++) {
        int u = tid + i * 256;
        int row = u >> 3, cb = u & 7;
        uint32_t so = swz((uint32_t)(row * 128 + cb * 16));
        CP16(sb + SW0 + so, W + (size_t)(m0 + row) * CH + cb * 8);
    }
    #pragma unroll
    for (int i = 0; i < 2; i++) {
        int u = tid + i * 256;
        int row = u >> 3, cb = u & 7;
        uint32_t so = swz((uint32_t)(row * 128 + cb * 16));
        CP16(sb + SX0 + so, Xb + (size_t)row * HW + t0 + cb * 8);
    }
    CP_COMMIT();

    int g = lane >> 3, r = lane & 7;
    uint32_t aoff0 = (uint32_t)((warp * 32 + (g & 1) * 8 + r) * 128 + (g >> 1) * 16);
    uint32_t aoff1 = aoff0 + 16 * 128;
    uint32_t boff  = (uint32_t)(((g & 1) * 8 + r) * 128 + (g >> 1) * 16);

    float acc0[8][4] = {}, acc1[8][4] = {};

    #pragma unroll
    for (int ck = 0; ck < 4; ck++) {
        if (ck < 3) {
            int c0 = (ck + 1) * 64;
            uint32_t wb = ((ck + 1) & 1) ? SW1 : SW0;
            uint32_t xs = ((ck + 1) & 1) ? SX1 : SX0;
            #pragma unroll
            for (int i = 0; i < 8; i++) {
                int u = tid + i * 256;
                int row = u >> 3, cb = u & 7;
                uint32_t so = swz((uint32_t)(row * 128 + cb * 16));
                CP16(sb + wb + so, W + (size_t)(m0 + row) * CH + c0 + cb * 8);
            }
            #pragma unroll
            for (int i = 0; i < 2; i++) {
                int u = tid + i * 256;
                int row = u >> 3, cb = u & 7;
                uint32_t so = swz((uint32_t)(row * 128 + cb * 16));
                CP16(sb + xs + so, Xb + (size_t)(c0 + row) * HW + t0 + cb * 8);
            }
            CP_COMMIT();
            CP_WAIT1();
        } else {
            CP_WAIT0();
        }
        __syncthreads();
        uint32_t Wb = sb + ((ck & 1) ? SW1 : SW0);
        uint32_t Xs = sb + ((ck & 1) ? SX1 : SX0);
        #pragma unroll
        for (int ks = 0; ks < 4; ks++) {
            uint32_t af0[4], af1[4];
            ldsm_x4(af0, Wb + swz(aoff0 + ks * 32));
            ldsm_x4(af1, Wb + swz(aoff1 + ks * 32));
            #pragma unroll
            for (int jj = 0; jj < 4; jj++) {
                uint32_t bf[4];
                ldsm_x4_t(bf, Xs + swz(boff + ks * 2048 + jj * 32));
                mma16816(acc0[2 * jj],     af0, bf[0], bf[1]);
                mma16816(acc0[2 * jj + 1], af0, bf[2], bf[3]);
                mma16816(acc1[2 * jj],     af1, bf[0], bf[1]);
                mma16816(acc1[2 * jj + 1], af1, bf[2], bf[3]);
            }
        }
        __syncthreads();
    }

    int r0 = warp * 32 + (lane >> 2);
    int cc = (lane & 3) * 2;
    int mA0 = m0 + r0, mB0 = mA0 + 8, mA1 = mA0 + 16, mB1 = mA0 + 24;
    float bA0 = bias[mA0], bB0 = bias[mB0], bA1 = bias[mA1], bB1 = bias[mB1];

    if (mode == 0) {
        float sA0 = ((mA0 % 192) < HDIM) ? QSCALE : 1.f;
        float sB0 = ((mB0 % 192) < HDIM) ? QSCALE : 1.f;
        float sA1 = ((mA1 % 192) < HDIM) ? QSCALE : 1.f;
        float sB1 = ((mB1 % 192) < HDIM) ? QSCALE : 1.f;
        #pragma unroll
        for (int nb = 0; nb < 8; nb++) {
            int col = nb * 8 + cc;
            *(uint32_t*)(sm + r0 * 144 + col * 2) =
                packbf((acc0[nb][0] + bA0) * sA0, (acc0[nb][1] + bA0) * sA0);
            *(uint32_t*)(sm + (r0 + 8) * 144 + col * 2) =
                packbf((acc0[nb][2] + bB0) * sB0, (acc0[nb][3] + bB0) * sB0);
            *(uint32_t*)(sm + (r0 + 16) * 144 + col * 2) =
                packbf((acc1[nb][0] + bA1) * sA1, (acc1[nb][1] + bA1) * sA1);
            *(uint32_t*)(sm + (r0 + 24) * 144 + col * 2) =
                packbf((acc1[nb][2] + bB1) * sB1, (acc1[nb][3] + bB1) * sB1);
        }
        __syncthreads();
        __nv_bfloat16* Yb = (__nv_bfloat16*)Y + ((size_t)b * M + m0) * HW + t0;
        #pragma unroll
        for (int i = 0; i < 8; i++) {
            int u = tid + i * 256;
            int row = u >> 3, cb = u & 7;
            uint4 v = *(const uint4*)(sm + row * 144 + cb * 16);
            *(uint4*)(Yb + (size_t)row * HW + cb * 8) = v;
        }
    } else {
        float* Of = (float*)sm;
        #pragma unroll
        for (int nb = 0; nb < 8; nb++) {
            int col = nb * 8 + cc;
            Of[r0 * 68 + col]            = acc0[nb][0] + bA0;
            Of[r0 * 68 + col + 1]        = acc0[nb][1] + bA0;
            Of[(r0 + 8) * 68 + col]      = acc0[nb][2] + bB0;
            Of[(r0 + 8) * 68 + col + 1]  = acc0[nb][3] + bB0;
            Of[(r0 + 16) * 68 + col]     = acc1[nb][0] + bA1;
            Of[(r0 + 16) * 68 + col + 1] = acc1[nb][1] + bA1;
            Of[(r0 + 24) * 68 + col]     = acc1[nb][2] + bB1;
            Of[(r0 + 24) * 68 + col + 1] = acc1[nb][3] + bB1;
        }
        __syncthreads();
        float* Yo = (float*)Y + ((size_t)b * M + m0) * HW + t0;
        const float* Xr = resid + ((size_t)b * CH + m0) * HW + t0;
        #pragma unroll
        for (int i = 0; i < 16; i++) {
            int u = tid + i * 256;
            int row = u >> 4, q4 = u & 15;
            float4 v  = *(const float4*)&Of[row * 68 + q4 * 4];
            float4 xr = *(const float4*)(Xr + (size_t)row * HW + q4 * 4);
            v.x = (v.x + xr.x) * INV_SQRT2;
            v.y = (v.y + xr.y) * INV_SQRT2;
            v.z = (v.z + xr.z) * INV_SQRT2;
            v.w = (v.w + xr.w) * INV_SQRT2;
            *(float4*)(Yo + (size_t)row * HW + q4 * 4) = v;
        }
    }
}

// ---------------------------------------------------------------------------
// mma.sync flash attention (R8/R12-proven, best-known): 32 q-rows/warp,
// 3-stage KV ring, one barrier per chunk, all-S-upfront then
// softmax(16)->PV(16) x4, MUFU ex2 only.
// ---------------------------------------------------------------------------
#define SQ0 0u
#define SQ1 8192u
#define KVS(s) (16384u + (uint32_t)(s) * 16384u)   // stage s: K at +0, V at +8192
#define ATT_SMEM 65536

__global__ void __launch_bounds__(128, 2)
attn_kernel(const __nv_bfloat16* __restrict__ qkv, __nv_bfloat16* __restrict__ out) {
    extern __shared__ __align__(128) char sm[];
    uint32_t sb = smem_u32(sm);
    int tid = threadIdx.x, warp = tid >> 5, lane = tid & 31;
    int qt0 = blockIdx.x * 128, h = blockIdx.y, b = blockIdx.z;

    const __nv_bfloat16* qb = qkv + ((size_t)(b * QKV_M + h * 192)) * HW;
    const __nv_bfloat16* kb = qb + (size_t)HDIM * HW;
    const __nv_bfloat16* vb = kb + (size_t)HDIM * HW;

    #pragma unroll
    for (int i = 0; i < 4; i++) {
        int u = tid + i * 128;
        int d = u >> 3, ub = u & 7;
        uint32_t so = swz((uint32_t)(d * 128 + ub * 16));
        CP16(sb + SQ0 + so,           qb + (size_t)d * HW + qt0 + ub * 8);
        CP16(sb + SQ1 + so,           qb + (size_t)d * HW + qt0 + 64 + ub * 8);
        CP16(sb + KVS(0) + so,        kb + (size_t)d * HW + ub * 8);
        CP16(sb + KVS(0) + 8192 + so, vb + (size_t)d * HW + ub * 8);
    }
    CP_COMMIT();
    #pragma unroll
    for (int i = 0; i < 4; i++) {
        int u = tid + i * 128;
        int d = u >> 3, ub = u & 7;
        uint32_t so = swz((uint32_t)(d * 128 + ub * 16));
        CP16(sb + KVS(1) + so,        kb + (size_t)d * HW + 64 + ub * 8);
        CP16(sb + KVS(1) + 8192 + so, vb + (size_t)d * HW + 64 + ub * 8);
    }
    CP_COMMIT();

    int g = lane >> 3, r = lane & 7;
    uint32_t koff = (uint32_t)(((g & 1) * 8 + r) * 128 + (g >> 1) * 16);
    uint32_t voff = (uint32_t)(((g >> 1) * 8 + r) * 128 + (g & 1) * 16);
    uint32_t qtile = (warp < 2) ? SQ0 : SQ1;
    int qcol = (warp & 1) * 32;
    uint32_t qoff0 = (uint32_t)(((g >> 1) * 8 + r) * 128 + (qcol + (g & 1) * 8) * 2);
    uint32_t qoff1 = qoff0 + 32;   // +16 queries * 2B

    float o0[8][4] = {}, o1[8][4] = {};
    float l[4] = {};
    uint32_t qa[2][4][4];

    for (int kt = 0; kt < 64; kt++) {
        if (kt < 63) { CP_WAIT1(); } else { CP_WAIT0(); }
        __syncthreads();
        if (kt + 2 < 64) {
            uint32_t st = KVS((kt + 2) % 3);
            const __nv_bfloat16* kc = kb + (kt + 2) * 64;
            const __nv_bfloat16* vc = vb + (kt + 2) * 64;
            #pragma unroll
            for (int i = 0; i < 4; i++) {
                int u = tid + i * 128;
                int d = u >> 3, ub = u & 7;
                uint32_t so = swz((uint32_t)(d * 128 + ub * 16));
                CP16(sb + st + so,        kc + (size_t)d * HW + ub * 8);
                CP16(sb + st + 8192 + so, vc + (size_t)d * HW + ub * 8);
            }
            CP_COMMIT();
        }

        uint32_t Kb = sb + KVS(kt % 3);
        uint32_t Vb = Kb + 8192;

        if (kt == 0) {
            #pragma unroll
            for (int ks = 0; ks < 4; ks++) {
                ldsm_x4_t(qa[0][ks], sb + qtile + swz(qoff0 + ks * 2048));
                ldsm_x4_t(qa[1][ks], sb + qtile + swz(qoff1 + ks * 2048));
            }
        }

        // ---- S = Q K^T for all 64 keys (both query sets)
        float s0[8][4] = {}, s1[8][4] = {};
        #pragma unroll
        for (int ks = 0; ks < 4; ks++) {
            #pragma unroll
            for (int jj = 0; jj < 4; jj++) {
                uint32_t f[4];
                ldsm_x4_t(f, Kb + swz(koff + ks * 2048 + jj * 32));
                mma16816(s0[2 * jj],     qa[0][ks], f[0], f[1]);
                mma16816(s0[2 * jj + 1], qa[0][ks], f[2], f[3]);
                mma16816(s1[2 * jj],     qa[1][ks], f[0], f[1]);
                mma16816(s1[2 * jj + 1], qa[1][ks], f[2], f[3]);
            }
        }

        // ---- interleaved: softmax(16 keys) then PV(16 keys), x4
        #pragma unroll
        for (int kk = 0; kk < 4; kk++) {
            uint32_t pk0[2][2], pk1[2][2];
            #pragma unroll
            for (int jj = 0; jj < 2; jj++) {
                int j = 2 * kk + jj;
                float a0 = ex2(s0[j][0]), a1 = ex2(s0[j][1]);
                float a2 = ex2(s0[j][2]), a3 = ex2(s0[j][3]);
                l[0] += a0 + a1; l[1] += a2 + a3;
                pk0[jj][0] = packbf(a0, a1); pk0[jj][1] = packbf(a2, a3);
                float b0 = ex2(s1[j][0]), b1 = ex2(s1[j][1]);
                float b2 = ex2(s1[j][2]), b3 = ex2(s1[j][3]);
                l[2] += b0 + b1; l[3] += b2 + b3;
                pk1[jj][0] = packbf(b0, b1); pk1[jj][1] = packbf(b2, b3);
            }
            uint32_t A0[4] = { pk0[0][0], pk0[0][1], pk0[1][0], pk0[1][1] };
            uint32_t A1[4] = { pk1[0][0], pk1[0][1], pk1[1][0], pk1[1][1] };
            #pragma unroll
            for (int dd = 0; dd < 4; dd++) {
                uint32_t f[4];
                ldsm_x4(f, Vb + swz(voff + dd * 2048 + kk * 32));
                mma16816(o0[2 * dd],     A0, f[0], f[1]);
                mma16816(o0[2 * dd + 1], A0, f[2], f[3]);
                mma16816(o1[2 * dd],     A1, f[0], f[1]);
                mma16816(o1[2 * dd + 1], A1, f[2], f[3]);
            }
        }
    }

    // ---- epilogue
    #pragma unroll
    for (int i = 0; i < 4; i++) {
        l[i] += __shfl_xor_sync(0xffffffffu, l[i], 1);
        l[i] += __shfl_xor_sync(0xffffffffu, l[i], 2);
    }
    float i0 = 1.f / l[0], i1 = 1.f / l[1], i2 = 1.f / l[2], i3 = 1.f / l[3];

    __syncthreads();
    float* Os = (float*)sm;                 // [64 d][132] fp32 (33.8KB reuse)
    int r0 = warp * 32 + (lane >> 2);
    int cc = (lane & 3) * 2;
    #pragma unroll
    for (int nb = 0; nb < 8; nb++) {
        int d0 = nb * 8 + cc;
        Os[d0 * 132 + r0]            = o0[nb][0] * i0;
        Os[(d0 + 1) * 132 + r0]      = o0[nb][1] * i0;
        Os[d0 * 132 + r0 + 8]        = o0[nb][2] * i1;
        Os[(d0 + 1) * 132 + r0 + 8]  = o0[nb][3] * i1;
        Os[d0 * 132 + r0 + 16]       = o1[nb][0] * i2;
        Os[(d0 + 1) * 132 + r0 + 16] = o1[nb][1] * i2;
        Os[d0 * 132 + r0 + 24]       = o1[nb][2] * i3;
        Os[(d0 + 1) * 132 + r0 + 24] = o1[nb][3] * i3;
    }
    __syncthreads();
    __nv_bfloat16* ob = out + ((size_t)(b * CH + h * HDIM)) * HW + qt0;
    #pragma unroll
    for (int i = 0; i < 16; i++) {
        int e = tid + i * 128;
        int d = e >> 5, q4 = e & 31;
        float4 v = *(const float4*)&Os[d * 132 + q4 * 4];
        uint2 w;
        w.x = packbf(v.x, v.y);
        w.y = packbf(v.z, v.w);
        *(uint2*)(ob + (size_t)d * HW + q4 * 4) = w;
    }
}

// ---------------------------------------------------------------------------
extern "C" void kernel_launch(void* const* d_in, const int* in_sizes, int n_in,
                              void* d_out, int out_size) {
    const float* x     = (const float*)d_in[0];
    const float* gamma = (const float*)d_in[1];
    const float* beta  = (const float*)d_in[2];
    const float* w_qkv = (const float*)d_in[3];
    const float* b_qkv = (const float*)d_in[4];
    const float* w_out = (const float*)d_in[5];
    const float* b_out = (const float*)d_in[6];
    float* out = (float*)d_out;

    __nv_bfloat16 *norm, *qkv, *att, *wq, *wo;
    cudaGetSymbolAddress((void**)&norm, g_norm);
    cudaGetSymbolAddress((void**)&qkv,  g_qkv);
    cudaGetSymbolAddress((void**)&att,  g_att);
    cudaGetSymbolAddress((void**)&wq,   g_wq);
    cudaGetSymbolAddress((void**)&wo,   g_wo);

    cudaFuncSetAttribute(attn_kernel, cudaFuncAttributeMaxDynamicSharedMemorySize, ATT_SMEM);
    cudaFuncSetAttribute(gemm_bf16, cudaFuncAttributeMaxDynamicSharedMemorySize, GEMM_SMEM);

    gn_wconv_kernel<<<BATCH * NGROUP + QKV_M * CH / 256, 256>>>(
        x, gamma, beta, norm, w_qkv, w_out, wq, wo);
    gemm_bf16<<<dim3(HW / 64, QKV_M / 256, BATCH), 256, GEMM_SMEM>>>(wq, norm, b_qkv, qkv, QKV_M, 0, nullptr);
    attn_kernel<<<dim3(HW / 128, NHEAD, BATCH), 128, ATT_SMEM>>>(qkv, att);
    gemm_bf16<<<dim3(HW / 64, CH / 256, BATCH), 256, GEMM_SMEM>>>(wo, att, b_out, out, CH, 1, x);
}

// round 16
// speedup vs baseline: 1.1117x; 1.0049x over previous
#include <cuda_runtime.h>
#include <cuda_bf16.h>
#include <cstdint>
#include <math.h>

#define BATCH 4
#define CH 256
#define HW 4096
#define NHEAD 4
#define HDIM 64
#define NGROUP 32
#define CPG 8
#define QKV_M 768

// softmax scale folded into q at qkv epilogue: 1/sqrt(256) * log2(e)
#define QSCALE (0.0625f * 1.4426950408889634f)
#define INV_SQRT2 0.70710678118654752f

// scratch (device globals: no allocations allowed)
__device__ __nv_bfloat16 g_norm[BATCH * CH * HW];
__device__ __nv_bfloat16 g_qkv [BATCH * QKV_M * HW];
__device__ __nv_bfloat16 g_att [BATCH * CH * HW];
__device__ __nv_bfloat16 g_wq  [QKV_M * CH];
__device__ __nv_bfloat16 g_wo  [CH * CH];

// ======================= PTX helpers (sm_100 baseline ISA) =================
__device__ __forceinline__ uint32_t smem_u32(const void* p) {
    uint32_t a;
    asm("{ .reg .u64 t; cvta.to.shared.u64 t, %1; cvt.u32.u64 %0, t; }" : "=r"(a) : "l"(p));
    return a;
}
__device__ __forceinline__ uint32_t swz(uint32_t off) {     // 16B-unit XOR swizzle, 128B rows
    return off ^ ((off >> 3) & 0x70u);
}
#define CP16(dst, src) \
    asm volatile("cp.async.ca.shared.global [%0], [%1], 16;" :: "r"(dst), "l"(src) : "memory")
#define CP_COMMIT() asm volatile("cp.async.commit_group;" ::: "memory")
#define CP_WAIT1()  asm volatile("cp.async.wait_group 1;" ::: "memory")
#define CP_WAIT0()  asm volatile("cp.async.wait_group 0;" ::: "memory")

__device__ __forceinline__ void ldsm_x4(uint32_t* f, uint32_t addr) {
    asm volatile("ldmatrix.sync.aligned.m8n8.x4.shared.b16 {%0,%1,%2,%3}, [%4];"
        : "=r"(f[0]), "=r"(f[1]), "=r"(f[2]), "=r"(f[3]) : "r"(addr));
}
__device__ __forceinline__ void ldsm_x4_t(uint32_t* f, uint32_t addr) {
    asm volatile("ldmatrix.sync.aligned.m8n8.x4.trans.shared.b16 {%0,%1,%2,%3}, [%4];"
        : "=r"(f[0]), "=r"(f[1]), "=r"(f[2]), "=r"(f[3]) : "r"(addr));
}
__device__ __forceinline__ void mma16816(float* d, const uint32_t* a, uint32_t b0, uint32_t b1) {
    asm volatile("mma.sync.aligned.m16n8k16.row.col.f32.bf16.bf16.f32 "
        "{%0,%1,%2,%3}, {%4,%5,%6,%7}, {%8,%9}, {%0,%1,%2,%3};"
        : "+f"(d[0]), "+f"(d[1]), "+f"(d[2]), "+f"(d[3])
        : "r"(a[0]), "r"(a[1]), "r"(a[2]), "r"(a[3]), "r"(b0), "r"(b1));
}
__device__ __forceinline__ float ex2(float x) {
    float r; asm("ex2.approx.ftz.f32 %0, %1;" : "=f"(r) : "f"(x)); return r;
}
__device__ __forceinline__ uint32_t packbf(float lo, float hi) {
    uint32_t r; asm("cvt.rn.bf16x2.f32 %0, %1, %2;" : "=r"(r) : "f"(hi), "f"(lo)); return r;
}

// ---------------------------------------------------------------------------
// GroupNorm -> bf16 (blocks 0..127, float4-vectorized) fused with weight
// conversion (blocks 128+).
// ---------------------------------------------------------------------------
__global__ void gn_wconv_kernel(const float* __restrict__ x,
                                const float* __restrict__ gamma,
                                const float* __restrict__ beta,
                                __nv_bfloat16* __restrict__ out,
                                const float* __restrict__ wq, const float* __restrict__ wo,
                                __nv_bfloat16* __restrict__ wqb, __nv_bfloat16* __restrict__ wob) {
    if (blockIdx.x >= BATCH * NGROUP) {
        int i = (blockIdx.x - BATCH * NGROUP) * 256 + threadIdx.x;
        if (i < QKV_M * CH) wqb[i] = __float2bfloat16(wq[i]);
        if (i < CH * CH)    wob[i] = __float2bfloat16(wo[i]);
        return;
    }
    int b = blockIdx.x >> 5;
    int g = blockIdx.x & 31;
    const float4* base4 = (const float4*)(x + ((size_t)b * CH + g * CPG) * HW);
    __nv_bfloat16* obase = out + ((size_t)b * CH + g * CPG) * HW;
    int tid = threadIdx.x;

    // pass 1: sums over 8192 float4s (32 per thread)
    float s = 0.f, ss = 0.f;
    #pragma unroll 8
    for (int i = tid; i < CPG * HW / 4; i += 256) {
        float4 v = base4[i];
        s  += (v.x + v.y) + (v.z + v.w);
        ss += (v.x * v.x + v.y * v.y) + (v.z * v.z + v.w * v.w);
    }
    __shared__ float rs[8], rss[8];
    #pragma unroll
    for (int m = 16; m; m >>= 1) {
        s  += __shfl_xor_sync(0xffffffffu, s,  m);
        ss += __shfl_xor_sync(0xffffffffu, ss, m);
    }
    if ((tid & 31) == 0) { rs[tid >> 5] = s; rss[tid >> 5] = ss; }
    __syncthreads();
    if (tid < 32) {
        s  = (tid < 8) ? rs[tid]  : 0.f;
        ss = (tid < 8) ? rss[tid] : 0.f;
        #pragma unroll
        for (int m = 4; m; m >>= 1) {
            s  += __shfl_xor_sync(0xffffffffu, s,  m);
            ss += __shfl_xor_sync(0xffffffffu, ss, m);
        }
        if (tid == 0) { rs[0] = s; rss[0] = ss; }
    }
    __syncthreads();
    const float invN = 1.f / (float)(CPG * HW);
    float mean = rs[0] * invN;
    float var  = rss[0] * invN - mean * mean;
    float rinv = rsqrtf(var + 1e-5f);

    // pass 2: normalize, 1 float4 -> 4 bf16 (uint2) per iteration
    #pragma unroll 8
    for (int i4 = tid; i4 < CPG * HW / 4; i4 += 256) {
        int c = g * CPG + (i4 >> 10);           // (i4*4)>>12
        float sc = rinv * gamma[c];
        float sh = beta[c] - mean * sc;
        float4 v = base4[i4];
        uint2 w;
        w.x = packbf(fmaf(v.x, sc, sh), fmaf(v.y, sc, sh));
        w.y = packbf(fmaf(v.z, sc, sh), fmaf(v.w, sc, sh));
        *(uint2*)&obase[i4 * 4] = w;
    }
}

// ---------------------------------------------------------------------------
// bf16 tensor-core GEMM (R12-proven): 256(M) x 64(T) tile, 256 threads.
// NEW: 128-reg cap (launch_bounds(256,2)) -> 2 CTAs/SM (was reg-limited to 1).
// ---------------------------------------------------------------------------
#define SW0 0u
#define SX0 32768u
#define SW1 40960u
#define SX1 73728u
#define GEMM_SMEM 81920

__global__ void __launch_bounds__(256, 2)
gemm_bf16(const __nv_bfloat16* __restrict__ W, const __nv_bfloat16* __restrict__ X,
          const float* __restrict__ bias, void* __restrict__ Y,
          int M, int mode, const float* __restrict__ resid) {
    extern __shared__ __align__(128) char sm[];
    uint32_t sb = smem_u32(sm);
    int tid = threadIdx.x, warp = tid >> 5, lane = tid & 31;
    int t0 = blockIdx.x * 64, m0 = blockIdx.y * 256, b = blockIdx.z;
    const __nv_bfloat16* Xb = X + (size_t)b * CH * HW;

    #pragma unroll
    for (int i = 0; i < 8; i++) {
        int u = tid + i * 256;
        int row = u >> 3, cb = u & 7;
        uint32_t so = swz((uint32_t)(row * 128 + cb * 16));
        CP16(sb + SW0 + so, W + (size_t)(m0 + row) * CH + cb * 8);
    }
    #pragma unroll
    for (int i = 0; i < 2; i++) {
        int u = tid + i * 256;
        int row = u >> 3, cb = u & 7;
        uint32_t so = swz((uint32_t)(row * 128 + cb * 16));
        CP16(sb + SX0 + so, Xb + (size_t)row * HW + t0 + cb * 8);
    }
    CP_COMMIT();

    int g = lane >> 3, r = lane & 7;
    uint32_t aoff0 = (uint32_t)((warp * 32 + (g & 1) * 8 + r) * 128 + (g >> 1) * 16);
    uint32_t aoff1 = aoff0 + 16 * 128;
    uint32_t boff  = (uint32_t)(((g & 1) * 8 + r) * 128 + (g >> 1) * 16);

    float acc0[8][4] = {}, acc1[8][4] = {};

    #pragma unroll
    for (int ck = 0; ck < 4; ck++) {
        if (ck < 3) {
            int c0 = (ck + 1) * 64;
            uint32_t wb = ((ck + 1) & 1) ? SW1 : SW0;
            uint32_t xs = ((ck + 1) & 1) ? SX1 : SX0;
            #pragma unroll
            for (int i = 0; i < 8; i++) {
                int u = tid + i * 256;
                int row = u >> 3, cb = u & 7;
                uint32_t so = swz((uint32_t)(row * 128 + cb * 16));
                CP16(sb + wb + so, W + (size_t)(m0 + row) * CH + c0 + cb * 8);
            }
            #pragma unroll
            for (int i = 0; i < 2; i++) {
                int u = tid + i * 256;
                int row = u >> 3, cb = u & 7;
                uint32_t so = swz((uint32_t)(row * 128 + cb * 16));
                CP16(sb + xs + so, Xb + (size_t)(c0 + row) * HW + t0 + cb * 8);
            }
            CP_COMMIT();
            CP_WAIT1();
        } else {
            CP_WAIT0();
        }
        __syncthreads();
        uint32_t Wb = sb + ((ck & 1) ? SW1 : SW0);
        uint32_t Xs = sb + ((ck & 1) ? SX1 : SX0);
        #pragma unroll
        for (int ks = 0; ks < 4; ks++) {
            uint32_t af0[4], af1[4];
            ldsm_x4(af0, Wb + swz(aoff0 + ks * 32));
            ldsm_x4(af1, Wb + swz(aoff1 + ks * 32));
            #pragma unroll
            for (int jj = 0; jj < 4; jj++) {
                uint32_t bf[4];
                ldsm_x4_t(bf, Xs + swz(boff + ks * 2048 + jj * 32));
                mma16816(acc0[2 * jj],     af0, bf[0], bf[1]);
                mma16816(acc0[2 * jj + 1], af0, bf[2], bf[3]);
                mma16816(acc1[2 * jj],     af1, bf[0], bf[1]);
                mma16816(acc1[2 * jj + 1], af1, bf[2], bf[3]);
            }
        }
        __syncthreads();
    }

    int r0 = warp * 32 + (lane >> 2);
    int cc = (lane & 3) * 2;
    int mA0 = m0 + r0, mB0 = mA0 + 8, mA1 = mA0 + 16, mB1 = mA0 + 24;
    float bA0 = bias[mA0], bB0 = bias[mB0], bA1 = bias[mA1], bB1 = bias[mB1];

    if (mode == 0) {
        float sA0 = ((mA0 % 192) < HDIM) ? QSCALE : 1.f;
        float sB0 = ((mB0 % 192) < HDIM) ? QSCALE : 1.f;
        float sA1 = ((mA1 % 192) < HDIM) ? QSCALE : 1.f;
        float sB1 = ((mB1 % 192) < HDIM) ? QSCALE : 1.f;
        #pragma unroll
        for (int nb = 0; nb < 8; nb++) {
            int col = nb * 8 + cc;
            *(uint32_t*)(sm + r0 * 144 + col * 2) =
                packbf((acc0[nb][0] + bA0) * sA0, (acc0[nb][1] + bA0) * sA0);
            *(uint32_t*)(sm + (r0 + 8) * 144 + col * 2) =
                packbf((acc0[nb][2] + bB0) * sB0, (acc0[nb][3] + bB0) * sB0);
            *(uint32_t*)(sm + (r0 + 16) * 144 + col * 2) =
                packbf((acc1[nb][0] + bA1) * sA1, (acc1[nb][1] + bA1) * sA1);
            *(uint32_t*)(sm + (r0 + 24) * 144 + col * 2) =
                packbf((acc1[nb][2] + bB1) * sB1, (acc1[nb][3] + bB1) * sB1);
        }
        __syncthreads();
        __nv_bfloat16* Yb = (__nv_bfloat16*)Y + ((size_t)b * M + m0) * HW + t0;
        #pragma unroll
        for (int i = 0; i < 8; i++) {
            int u = tid + i * 256;
            int row = u >> 3, cb = u & 7;
            uint4 v = *(const uint4*)(sm + row * 144 + cb * 16);
            *(uint4*)(Yb + (size_t)row * HW + cb * 8) = v;
        }
    } else {
        float* Of = (float*)sm;
        #pragma unroll
        for (int nb = 0; nb < 8; nb++) {
            int col = nb * 8 + cc;
            Of[r0 * 68 + col]            = acc0[nb][0] + bA0;
            Of[r0 * 68 + col + 1]        = acc0[nb][1] + bA0;
            Of[(r0 + 8) * 68 + col]      = acc0[nb][2] + bB0;
            Of[(r0 + 8) * 68 + col + 1]  = acc0[nb][3] + bB0;
            Of[(r0 + 16) * 68 + col]     = acc1[nb][0] + bA1;
            Of[(r0 + 16) * 68 + col + 1] = acc1[nb][1] + bA1;
            Of[(r0 + 24) * 68 + col]     = acc1[nb][2] + bB1;
            Of[(r0 + 24) * 68 + col + 1] = acc1[nb][3] + bB1;
        }
        __syncthreads();
        float* Yo = (float*)Y + ((size_t)b * M + m0) * HW + t0;
        const float* Xr = resid + ((size_t)b * CH + m0) * HW + t0;
        #pragma unroll
        for (int i = 0; i < 16; i++) {
            int u = tid + i * 256;
            int row = u >> 4, q4 = u & 15;
            float4 v  = *(const float4*)&Of[row * 68 + q4 * 4];
            float4 xr = *(const float4*)(Xr + (size_t)row * HW + q4 * 4);
            v.x = (v.x + xr.x) * INV_SQRT2;
            v.y = (v.y + xr.y) * INV_SQRT2;
            v.z = (v.z + xr.z) * INV_SQRT2;
            v.w = (v.w + xr.w) * INV_SQRT2;
            *(float4*)(Yo + (size_t)row * HW + q4 * 4) = v;
        }
    }
}

// ---------------------------------------------------------------------------
// mma.sync flash attention (R8/R12-proven, best-known): 32 q-rows/warp,
// 3-stage KV ring, one barrier per chunk, all-S-upfront then
// softmax(16)->PV(16) x4, MUFU ex2 only.
// ---------------------------------------------------------------------------
#define SQ0 0u
#define SQ1 8192u
#define KVS(s) (16384u + (uint32_t)(s) * 16384u)   // stage s: K at +0, V at +8192
#define ATT_SMEM 65536

__global__ void __launch_bounds__(128, 2)
attn_kernel(const __nv_bfloat16* __restrict__ qkv, __nv_bfloat16* __restrict__ out) {
    extern __shared__ __align__(128) char sm[];
    uint32_t sb = smem_u32(sm);
    int tid = threadIdx.x, warp = tid >> 5, lane = tid & 31;
    int qt0 = blockIdx.x * 128, h = blockIdx.y, b = blockIdx.z;

    const __nv_bfloat16* qb = qkv + ((size_t)(b * QKV_M + h * 192)) * HW;
    const __nv_bfloat16* kb = qb + (size_t)HDIM * HW;
    const __nv_bfloat16* vb = kb + (size_t)HDIM * HW;

    #pragma unroll
    for (int i = 0; i < 4; i++) {
        int u = tid + i * 128;
        int d = u >> 3, ub = u & 7;
        uint32_t so = swz((uint32_t)(d * 128 + ub * 16));
        CP16(sb + SQ0 + so,           qb + (size_t)d * HW + qt0 + ub * 8);
        CP16(sb + SQ1 + so,           qb + (size_t)d * HW + qt0 + 64 + ub * 8);
        CP16(sb + KVS(0) + so,        kb + (size_t)d * HW + ub * 8);
        CP16(sb + KVS(0) + 8192 + so, vb + (size_t)d * HW + ub * 8);
    }
    CP_COMMIT();
    #pragma unroll
    for (int i = 0; i < 4; i++) {
        int u = tid + i * 128;
        int d = u >> 3, ub = u & 7;
        uint32_t so = swz((uint32_t)(d * 128 + ub * 16));
        CP16(sb + KVS(1) + so,        kb + (size_t)d * HW + 64 + ub * 8);
        CP16(sb + KVS(1) + 8192 + so, vb + (size_t)d * HW + 64 + ub * 8);
    }
    CP_COMMIT();

    int g = lane >> 3, r = lane & 7;
    uint32_t koff = (uint32_t)(((g & 1) * 8 + r) * 128 + (g >> 1) * 16);
    uint32_t voff = (uint32_t)(((g >> 1) * 8 + r) * 128 + (g & 1) * 16);
    uint32_t qtile = (warp < 2) ? SQ0 : SQ1;
    int qcol = (warp & 1) * 32;
    uint32_t qoff0 = (uint32_t)(((g >> 1) * 8 + r) * 128 + (qcol + (g & 1) * 8) * 2);
    uint32_t qoff1 = qoff0 + 32;   // +16 queries * 2B

    float o0[8][4] = {}, o1[8][4] = {};
    float l[4] = {};
    uint32_t qa[2][4][4];

    for (int kt = 0; kt < 64; kt++) {
        if (kt < 63) { CP_WAIT1(); } else { CP_WAIT0(); }
        __syncthreads();
        if (kt + 2 < 64) {
            uint32_t st = KVS((kt + 2) % 3);
            const __nv_bfloat16* kc = kb + (kt + 2) * 64;
            const __nv_bfloat16* vc = vb + (kt + 2) * 64;
            #pragma unroll
            for (int i = 0; i < 4; i++) {
                int u = tid + i * 128;
                int d = u >> 3, ub = u & 7;
                uint32_t so = swz((uint32_t)(d * 128 + ub * 16));
                CP16(sb + st + so,        kc + (size_t)d * HW + ub * 8);
                CP16(sb + st + 8192 + so, vc + (size_t)d * HW + ub * 8);
            }
            CP_COMMIT();
        }

        uint32_t Kb = sb + KVS(kt % 3);
        uint32_t Vb = Kb + 8192;

        if (kt == 0) {
            #pragma unroll
            for (int ks = 0; ks < 4; ks++) {
                ldsm_x4_t(qa[0][ks], sb + qtile + swz(qoff0 + ks * 2048));
                ldsm_x4_t(qa[1][ks], sb + qtile + swz(qoff1 + ks * 2048));
            }
        }

        // ---- S = Q K^T for all 64 keys (both query sets)
        float s0[8][4] = {}, s1[8][4] = {};
        #pragma unroll
        for (int ks = 0; ks < 4; ks++) {
            #pragma unroll
            for (int jj = 0; jj < 4; jj++) {
                uint32_t f[4];
                ldsm_x4_t(f, Kb + swz(koff + ks * 2048 + jj * 32));
                mma16816(s0[2 * jj],     qa[0][ks], f[0], f[1]);
                mma16816(s0[2 * jj + 1], qa[0][ks], f[2], f[3]);
                mma16816(s1[2 * jj],     qa[1][ks], f[0], f[1]);
                mma16816(s1[2 * jj + 1], qa[1][ks], f[2], f[3]);
            }
        }

        // ---- interleaved: softmax(16 keys) then PV(16 keys), x4
        #pragma unroll
        for (int kk = 0; kk < 4; kk++) {
            uint32_t pk0[2][2], pk1[2][2];
            #pragma unroll
            for (int jj = 0; jj < 2; jj++) {
                int j = 2 * kk + jj;
                float a0 = ex2(s0[j][0]), a1 = ex2(s0[j][1]);
                float a2 = ex2(s0[j][2]), a3 = ex2(s0[j][3]);
                l[0] += a0 + a1; l[1] += a2 + a3;
                pk0[jj][0] = packbf(a0, a1); pk0[jj][1] = packbf(a2, a3);
                float b0 = ex2(s1[j][0]), b1 = ex2(s1[j][1]);
                float b2 = ex2(s1[j][2]), b3 = ex2(s1[j][3]);
                l[2] += b0 + b1; l[3] += b2 + b3;
                pk1[jj][0] = packbf(b0, b1); pk1[jj][1] = packbf(b2, b3);
            }
            uint32_t A0[4] = { pk0[0][0], pk0[0][1], pk0[1][0], pk0[1][1] };
            uint32_t A1[4] = { pk1[0][0], pk1[0][1], pk1[1][0], pk1[1][1] };
            #pragma unroll
            for (int dd = 0; dd < 4; dd++) {
                uint32_t f[4];
                ldsm_x4(f, Vb + swz(voff + dd * 2048 + kk * 32));
                mma16816(o0[2 * dd],     A0, f[0], f[1]);
                mma16816(o0[2 * dd + 1], A0, f[2], f[3]);
                mma16816(o1[2 * dd],     A1, f[0], f[1]);
                mma16816(o1[2 * dd + 1], A1, f[2], f[3]);
            }
        }
    }

    // ---- epilogue
    #pragma unroll
    for (int i = 0; i < 4; i++) {
        l[i] += __shfl_xor_sync(0xffffffffu, l[i], 1);
        l[i] += __shfl_xor_sync(0xffffffffu, l[i], 2);
    }
    float i0 = 1.f / l[0], i1 = 1.f / l[1], i2 = 1.f / l[2], i3 = 1.f / l[3];

    __syncthreads();
    float* Os = (float*)sm;                 // [64 d][132] fp32 (33.8KB reuse)
    int r0 = warp * 32 + (lane >> 2);
    int cc = (lane & 3) * 2;
    #pragma unroll
    for (int nb = 0; nb < 8; nb++) {
        int d0 = nb * 8 + cc;
        Os[d0 * 132 + r0]            = o0[nb][0] * i0;
        Os[(d0 + 1) * 132 + r0]      = o0[nb][1] * i0;
        Os[d0 * 132 + r0 + 8]        = o0[nb][2] * i1;
        Os[(d0 + 1) * 132 + r0 + 8]  = o0[nb][3] * i1;
        Os[d0 * 132 + r0 + 16]       = o1[nb][0] * i2;
        Os[(d0 + 1) * 132 + r0 + 16] = o1[nb][1] * i2;
        Os[d0 * 132 + r0 + 24]       = o1[nb][2] * i3;
        Os[(d0 + 1) * 132 + r0 + 24] = o1[nb][3] * i3;
    }
    __syncthreads();
    __nv_bfloat16* ob = out + ((size_t)(b * CH + h * HDIM)) * HW + qt0;
    #pragma unroll
    for (int i = 0; i < 16; i++) {
        int e = tid + i * 128;
        int d = e >> 5, q4 = e & 31;
        float4 v = *(const float4*)&Os[d * 132 + q4 * 4];
        uint2 w;
        w.x = packbf(v.x, v.y);
        w.y = packbf(v.z, v.w);
        *(uint2*)(ob + (size_t)d * HW + q4 * 4) = w;
    }
}

// ---------------------------------------------------------------------------
extern "C" void kernel_launch(void* const* d_in, const int* in_sizes, int n_in,
                              void* d_out, int out_size) {
    const float* x     = (const float*)d_in[0];
    const float* gamma = (const float*)d_in[1];
    const float* beta  = (const float*)d_in[2];
    const float* w_qkv = (const float*)d_in[3];
    const float* b_qkv = (const float*)d_in[4];
    const float* w_out = (const float*)d_in[5];
    const float* b_out = (const float*)d_in[6];
    float* out = (float*)d_out;

    __nv_bfloat16 *norm, *qkv, *att, *wq, *wo;
    cudaGetSymbolAddress((void**)&norm, g_norm);
    cudaGetSymbolAddress((void**)&qkv,  g_qkv);
    cudaGetSymbolAddress((void**)&att,  g_att);
    cudaGetSymbolAddress((void**)&wq,   g_wq);
    cudaGetSymbolAddress((void**)&wo,   g_wo);

    cudaFuncSetAttribute(attn_kernel, cudaFuncAttributeMaxDynamicSharedMemorySize, ATT_SMEM);
    cudaFuncSetAttribute(gemm_bf16, cudaFuncAttributeMaxDynamicSharedMemorySize, GEMM_SMEM);

    gn_wconv_kernel<<<BATCH * NGROUP + QKV_M * CH / 256, 256>>>(
        x, gamma, beta, norm, w_qkv, w_out, wq, wo);
    gemm_bf16<<<dim3(HW / 64, QKV_M / 256, BATCH), 256, GEMM_SMEM>>>(wq, norm, b_qkv, qkv, QKV_M, 0, nullptr);
    attn_kernel<<<dim3(HW / 128, NHEAD, BATCH), 128, ATT_SMEM>>>(qkv, att);
    gemm_bf16<<<dim3(HW / 64, CH / 256, BATCH), 256, GEMM_SMEM>>>(wo, att, b_out, out, CH, 1, x);
}